// round 4
// baseline (speedup 1.0000x reference)
#include <cuda_runtime.h>
#include <cooperative_groups.h>
#include <math.h>
#include <stdint.h>

namespace cg = cooperative_groups;

// ---------------------------------------------------------------------------
// LogNCDE depth-2 log-ODE scan, 4-CTA cluster per batch element.
// Rank r owns channels {2r,2r+1} and Wv2 rows [128r,128r+128).
// Weights in registers; warp-level shfl reductions (lane = row-pair x k-quarter);
// cluster exchanges via DSMEM stores + mbarrier arrive/wait (no cluster.sync).
// ---------------------------------------------------------------------------

namespace {
constexpr int kB   = 32;
constexpr int kT   = 2049;
constexpr int kD   = 8;
constexpr int kS   = 64;
constexpr int kH   = 128;
constexpr int kP   = 28;
constexpr int kNW  = 128;
constexpr int kWin = 16;
constexpr int kOut = 8;
constexpr int CL   = 4;
constexpr int NT   = 256;

// shared-memory layout (float offsets; float4-aligned)
constexpr int OFF_SIGS  = 0;         // [n<128][36]
constexpr int OFF_BV0   = 4608;      // 128
constexpr int OFF_BV1   = 4736;      // 128
constexpr int OFF_BV2S  = 4864;      // 128
constexpr int OFF_WR    = 4992;      // [o<8][a<64]
constexpr int OFF_BR    = 5504;      // 8 (+pad)
constexpr int OFF_H     = 5520;      // 64
constexpr int OFF_Z0    = 5584;      // 128
constexpr int OFF_D0    = 5712;      // 128
constexpr int OFF_Z1    = 5840;      // 128
constexpr int OFF_D1    = 5968;      // 128
constexpr int OFF_V     = 6096;      // 2 x 512 double buffer
constexpr int OFF_TDS   = 7120;      // 128
constexpr int OFF_C     = 7248;      // 16
constexpr int OFF_WT    = 7264;      // 2 x 64
constexpr int OFF_PT    = 7392;      // 2 x 128
constexpr int OFF_UT    = 7648;      // 2 x 128
constexpr int OFF_RD    = 7904;      // 128
constexpr int OFF_RSLOT = 8032;      // 4 x 64
constexpr int OFF_MBAR  = 8288;      // 16 bytes: VBAR @ +0, RBAR @ +8
constexpr int SMEMF     = 8296;      // ~33 KB
}  // namespace

static __device__ const int c_II[kP] =
    {0,0,0,0,0,0,0,1,1,1,1,1,1,2,2,2,2,2,3,3,3,3,4,4,4,5,5,6};
static __device__ const int c_JJ[kP] =
    {1,2,3,4,5,6,7,2,3,4,5,6,7,3,4,5,6,7,4,5,6,7,5,6,7,6,7,7};

__device__ __forceinline__ int pidx(int i, int j) {   // Lyndon pair index, i<j
    return 7 * i - (i * (i - 1)) / 2 + (j - i - 1);
}
__device__ __forceinline__ float dot4(float4 w, float4 v, float acc) {
    acc = fmaf(w.x, v.x, acc); acc = fmaf(w.y, v.y, acc);
    acc = fmaf(w.z, v.z, acc); acc = fmaf(w.w, v.w, acc);
    return acc;
}
__device__ __forceinline__ float tanh_ap(float x) {
    float r; asm("tanh.approx.f32 %0, %1;" : "=f"(r) : "f"(x)); return r;
}
// softplus value + sigmoid derivative from one exp
__device__ __forceinline__ void sp_sg(float s, float& z, float& d) {
    if (s > 20.f) { z = s; d = 1.f; }
    else {
        float e = __expf(s);
        z = __logf(1.f + e);
        d = e / (1.f + e);
    }
}
// accurate versions for the one-time h0 path
__device__ __forceinline__ float sp_f(float x) {
    return (x > 20.f) ? x : log1pf(expf(x));
}

__device__ __forceinline__ uint32_t cvta_smem(const void* p) {
    uint32_t a;
    asm("{ .reg .u64 t; cvta.to.shared.u64 t, %1; cvt.u32.u64 %0, t; }"
        : "=r"(a) : "l"(p));
    return a;
}
__device__ __forceinline__ uint32_t mapa_u32(uint32_t addr, int rank) {
    uint32_t r;
    asm("mapa.shared::cluster.u32 %0, %1, %2;" : "=r"(r) : "r"(addr), "r"(rank));
    return r;
}
__device__ __forceinline__ void mbar_init(uint32_t addr, uint32_t count) {
    asm volatile("mbarrier.init.shared.b64 [%0], %1;" :: "r"(addr), "r"(count) : "memory");
}
__device__ __forceinline__ void mbar_arrive_rel_cluster(uint32_t addr) {
    asm volatile("mbarrier.arrive.release.cluster.shared::cluster.b64 _, [%0];"
                 :: "r"(addr) : "memory");
}
__device__ __forceinline__ void mbar_wait_parity_cluster(uint32_t addr, uint32_t par) {
    uint32_t done;
    asm volatile(
        "{\n\t.reg .pred p;\n\t"
        "mbarrier.try_wait.parity.acquire.cluster.shared::cta.b64 p, [%1], %2;\n\t"
        "selp.b32 %0, 1, 0, p;\n\t}"
        : "=r"(done) : "r"(addr), "r"(par) : "memory");
    if (!done) {
        asm volatile(
            "{\n\t.reg .pred P1;\n\t"
            "WL_%=:\n\t"
            "mbarrier.try_wait.parity.acquire.cluster.shared::cta.b64 P1, [%0], %1, 0x989680;\n\t"
            "@P1 bra.uni WD_%=;\n\t"
            "bra.uni WL_%=;\n\t"
            "WD_%=:\n\t}"
            :: "r"(addr), "r"(par) : "memory");
    }
}

__global__ __launch_bounds__(NT, 1) __cluster_dims__(CL, 1, 1)
void logncde_shfl_kernel(
    const float* __restrict__ x,
    const float* __restrict__ Wi0, const float* __restrict__ bi0,
    const float* __restrict__ Wi1, const float* __restrict__ bi1,
    const float* __restrict__ Wi2, const float* __restrict__ bi2,
    const float* __restrict__ Wv0, const float* __restrict__ bv0,
    const float* __restrict__ Wv1, const float* __restrict__ bv1,
    const float* __restrict__ Wv2, const float* __restrict__ bv2,
    const float* __restrict__ Wr,  const float* __restrict__ br,
    float* __restrict__ out)
{
    extern __shared__ float sm[];
    cg::cluster_group cluster = cg::this_cluster();
    const int t    = threadIdx.x;
    const int rank = (int)cluster.block_rank();
    const int b    = blockIdx.x >> 2;
    const int d0g  = 2 * rank;
    const int w    = t >> 5;          // warp id
    const int l    = t & 31;          // lane
    const int rp   = l >> 2;          // row-pair within warp (0..7)
    const int q    = l & 3;           // k-quarter (0..3)
    const int r0   = w * 16 + rp * 2; // first owned output row
    const int r1   = r0 + 1;

    // peer data pointers
    float* peer[CL - 1];
    #pragma unroll
    for (int p = 1; p < CL; p++)
        peer[p - 1] = cluster.map_shared_rank(sm, (rank + p) & (CL - 1));

    // mbarrier addresses (local + mapped for every rank)
    const uint32_t smb    = cvta_smem(sm);
    const uint32_t vbar_l = smb + OFF_MBAR * 4;
    const uint32_t rbar_l = vbar_l + 8;
    uint32_t vbar_r[CL], rbar_r[CL];
    #pragma unroll
    for (int p = 0; p < CL; p++) {
        vbar_r[p] = mapa_u32(vbar_l, p);
        rbar_r[p] = mapa_u32(rbar_l, p);
    }
    if (t == 0) {
        mbar_init(vbar_l, 128);   // 32 lanes x 4 ranks
        mbar_init(rbar_l, 64);    // 16 lanes x 4 ranks
        asm volatile("fence.mbarrier_init.release.cluster;" ::: "memory");
    }

    // ---- register weight tiles: row-pair (r0,r1) x k-quarter q ----
    float4 w0r[8], w1r[16], w2r[16];
    {
        const float4* W0 = (const float4*)Wv0;   // [128][16] f4
        #pragma unroll
        for (int j = 0; j < 4; j++) {
            w0r[j]     = W0[r0 * 16 + q * 4 + j];
            w0r[4 + j] = W0[r1 * 16 + q * 4 + j];
        }
        const float4* W1 = (const float4*)Wv1;   // [128][32] f4
        #pragma unroll
        for (int j = 0; j < 8; j++) {
            w1r[j]     = W1[r0 * 32 + q * 8 + j];
            w1r[8 + j] = W1[r1 * 32 + q * 8 + j];
        }
        const float4* W2 = (const float4*)Wv2;   // [512][32] f4
        #pragma unroll
        for (int j = 0; j < 8; j++) {
            w2r[j]     = W2[(kH * rank + r0) * 32 + q * 8 + j];
            w2r[8 + j] = W2[(kH * rank + r1) * 32 + q * 8 + j];
        }
    }

    // ---- one-time smem staging ----
    for (int i = t; i < kH; i += NT) {
        sm[OFF_BV0 + i]  = bv0[i];
        sm[OFF_BV1 + i]  = bv1[i];
        sm[OFF_BV2S + i] = bv2[kH * rank + i];
    }
    for (int i = t; i < kOut * kS; i += NT) sm[OFF_WR + i] = Wr[i];
    if (t < kOut) sm[OFF_BR + t] = br[t];

    // ---- one-time: depth-2 log-signatures ----
    if (t < kNW) {
        const float* xb = x + (size_t)b * kT * kD + (size_t)t * kWin * kD;
        float cum[kD], prev[kD], Mm[kD * kD];
        #pragma unroll
        for (int i = 0; i < kD; i++) { cum[i] = 0.f; prev[i] = xb[i]; }
        #pragma unroll
        for (int i = 0; i < kD * kD; i++) Mm[i] = 0.f;
        for (int ww = 0; ww < kWin; ww++) {
            float dl[kD];
            #pragma unroll
            for (int j = 0; j < kD; j++) {
                float c = xb[(ww + 1) * kD + j];
                dl[j] = c - prev[j];
                prev[j] = c;
            }
            #pragma unroll
            for (int i = 0; i < kD; i++)
                #pragma unroll
                for (int j = 0; j < kD; j++)
                    Mm[i * kD + j] = fmaf(cum[i], dl[j], Mm[i * kD + j]);
            #pragma unroll
            for (int i = 0; i < kD; i++) cum[i] += dl[i];
        }
        float* sgw = &sm[OFF_SIGS + t * 36];
        #pragma unroll
        for (int i = 0; i < kD; i++) sgw[i] = cum[i];
        #pragma unroll
        for (int p = 0; p < kP; p++) {
            int i = c_II[p], j = c_JJ[p];
            sgw[8 + p] = 0.5f * (Mm[i * kD + j] - Mm[j * kD + i]);
        }
    }
    __syncthreads();

    // ---- one-time: initial MLP h0 (accurate path; replicated) ----
    {
        const float* x0 = x + (size_t)b * kT * kD;
        if (t < kH) {
            float acc = bi0[t];
            #pragma unroll
            for (int k = 0; k < kD; k++) acc = fmaf(Wi0[t * kD + k], x0[k], acc);
            sm[OFF_Z0 + t] = sp_f(acc);
        }
        __syncthreads();
        if (t < kH) {
            float acc = bi1[t];
            #pragma unroll 16
            for (int k = 0; k < kH; k++) acc = fmaf(Wi1[t * kH + k], sm[OFF_Z0 + k], acc);
            sm[OFF_Z1 + t] = sp_f(acc);
        }
        __syncthreads();
        if (t < kS) {
            float acc = bi2[t];
            #pragma unroll 16
            for (int k = 0; k < kH; k++) acc = fmaf(Wi2[t * kH + k], sm[OFF_Z1 + k], acc);
            sm[OFF_H + t] = acc;
        }
        __syncthreads();
    }

    cluster.sync();   // staging + mbarrier init visible cluster-wide

    float4*       Vloc4  = (float4*)&sm[OFF_V];
    const float4* rd4    = (const float4*)&sm[OFF_RD];
    float4*       rslot4 = (float4*)&sm[OFF_RSLOT];

    // ============================ scan loop ============================
    for (int n = 0; n < kNW; n++) {
        const float* sgn = &sm[OFF_SIGS + n * 36];
        const int parV  = (n & 1) * 512;   // float offset
        const int parV4 = (n & 1) * 128;   // float4 offset
        const uint32_t par = (uint32_t)(n & 1);

        // --- A: z0 = sp(Wv0 h + bv0); spare lanes: readout + C coeffs
        {
            const float4* h4 = (const float4*)&sm[OFF_H];
            float acc0 = 0.f, acc1 = 0.f;
            #pragma unroll
            for (int j = 0; j < 4; j++) {
                float4 hv = h4[q * 4 + j];
                acc0 = dot4(w0r[j], hv, acc0);
                acc1 = dot4(w0r[4 + j], hv, acc1);
            }
            acc0 += __shfl_xor_sync(0xffffffffu, acc0, 1);
            acc0 += __shfl_xor_sync(0xffffffffu, acc0, 2);
            acc1 += __shfl_xor_sync(0xffffffffu, acc1, 1);
            acc1 += __shfl_xor_sync(0xffffffffu, acc1, 2);
            if (q == 0) {
                float z, d;
                sp_sg(acc0 + sm[OFF_BV0 + r0], z, d);
                sm[OFF_Z0 + r0] = z; sm[OFF_D0 + r0] = d;
                sp_sg(acc1 + sm[OFF_BV0 + r1], z, d);
                sm[OFF_Z0 + r1] = z; sm[OFF_D0 + r1] = d;
            } else if (q == 2) {
                if (rank == 0) {       // readout of h_n, output o = w
                    float acc = 0.f;
                    #pragma unroll
                    for (int kk = 0; kk < 8; kk++)
                        acc = fmaf(sm[OFF_WR + w * kS + rp * 8 + kk],
                                   sm[OFF_H + rp * 8 + kk], acc);
                    acc += __shfl_xor_sync(0x44444444u, acc, 4);
                    acc += __shfl_xor_sync(0x44444444u, acc, 8);
                    acc += __shfl_xor_sync(0x44444444u, acc, 16);
                    if (l == 2)
                        out[((size_t)b * (kNW + 1) + n) * kOut + w] =
                            acc + sm[OFF_BR + w];
                }
            } else if (q == 3 && w < 2) {
                int dl = w, e = rp;
                int d = d0g + dl;
                float v = 0.f;
                if (e < d)      v =  sgn[8 + pidx(e, d)];
                else if (e > d) v = -sgn[8 + pidx(d, e)];
                sm[OFF_C + dl * 8 + e] = v;
            }
        }
        __syncthreads();

        // --- B: z1 = sp(Wv1 z0 + bv1)
        {
            const float4* z4 = (const float4*)&sm[OFF_Z0];
            float acc0 = 0.f, acc1 = 0.f;
            #pragma unroll
            for (int j = 0; j < 8; j++) {
                float4 zv = z4[q * 8 + j];
                acc0 = dot4(w1r[j], zv, acc0);
                acc1 = dot4(w1r[8 + j], zv, acc1);
            }
            acc0 += __shfl_xor_sync(0xffffffffu, acc0, 1);
            acc0 += __shfl_xor_sync(0xffffffffu, acc0, 2);
            acc1 += __shfl_xor_sync(0xffffffffu, acc1, 1);
            acc1 += __shfl_xor_sync(0xffffffffu, acc1, 2);
            if (q == 0) {
                float z, d;
                sp_sg(acc0 + sm[OFF_BV1 + r0], z, d);
                sm[OFF_Z1 + r0] = z; sm[OFF_D1 + r0] = d;
                sp_sg(acc1 + sm[OFF_BV1 + r1], z, d);
                sm[OFF_Z1 + r1] = z; sm[OFF_D1 + r1] = d;
            }
        }
        __syncthreads();

        // --- C: V slice = tanh(Wv2s z1 + bv2s)
        {
            const float4* z4 = (const float4*)&sm[OFF_Z1];
            float acc0 = 0.f, acc1 = 0.f;
            #pragma unroll
            for (int j = 0; j < 8; j++) {
                float4 zv = z4[q * 8 + j];
                acc0 = dot4(w2r[j], zv, acc0);
                acc1 = dot4(w2r[8 + j], zv, acc1);
            }
            acc0 += __shfl_xor_sync(0xffffffffu, acc0, 1);
            acc0 += __shfl_xor_sync(0xffffffffu, acc0, 2);
            acc1 += __shfl_xor_sync(0xffffffffu, acc1, 1);
            acc1 += __shfl_xor_sync(0xffffffffu, acc1, 2);
            if (q == 0) {
                float v0 = tanh_ap(acc0 + sm[OFF_BV2S + r0]);
                float v1 = tanh_ap(acc1 + sm[OFF_BV2S + r1]);
                sm[OFF_V + parV + kH * rank + r0] = v0;
                sm[OFF_V + parV + kH * rank + r1] = v1;
                sm[OFF_TDS + r0] = 1.f - v0 * v0;
                sm[OFF_TDS + r1] = 1.f - v1 * v1;
            }
        }
        __syncthreads();
        // V exchange: warp0 pushes slice to peers; per-lane release arrives
        if (t < 32) {
            int idx = parV4 + 32 * rank + t;
            float4 vv = Vloc4[idx];
            ((float4*)peer[0])[(OFF_V >> 2) + idx] = vv;
            ((float4*)peer[1])[(OFF_V >> 2) + idx] = vv;
            ((float4*)peer[2])[(OFF_V >> 2) + idx] = vv;
            #pragma unroll
            for (int p = 0; p < CL; p++) mbar_arrive_rel_cluster(vbar_r[p]);
        }
        mbar_wait_parity_cluster(vbar_l, par);

        // --- D: tangents w_d = sum_e C[d,e] V_e (own 2 channels)
        if (t < kH) {
            int dl = t >> 6, a_ = t & 63;
            float acc = 0.f;
            #pragma unroll
            for (int e = 0; e < kD; e++)
                acc = fmaf(sm[OFF_C + dl * 8 + e], sm[OFF_V + parV + e * kS + a_], acc);
            sm[OFF_WT + dl * kS + a_] = acc;
        }
        __syncthreads();

        // --- E: pt_c = D0 .* (Wv0 wt_c), 2 channels
        {
            const float4* wt4 = (const float4*)&sm[OFF_WT];
            float a00 = 0.f, a01 = 0.f, a10 = 0.f, a11 = 0.f;
            #pragma unroll
            for (int j = 0; j < 4; j++) {
                float4 v0 = wt4[q * 4 + j];
                float4 v1 = wt4[16 + q * 4 + j];
                a00 = dot4(w0r[j], v0, a00);
                a01 = dot4(w0r[4 + j], v0, a01);
                a10 = dot4(w0r[j], v1, a10);
                a11 = dot4(w0r[4 + j], v1, a11);
            }
            a00 += __shfl_xor_sync(0xffffffffu, a00, 1);
            a00 += __shfl_xor_sync(0xffffffffu, a00, 2);
            a01 += __shfl_xor_sync(0xffffffffu, a01, 1);
            a01 += __shfl_xor_sync(0xffffffffu, a01, 2);
            a10 += __shfl_xor_sync(0xffffffffu, a10, 1);
            a10 += __shfl_xor_sync(0xffffffffu, a10, 2);
            a11 += __shfl_xor_sync(0xffffffffu, a11, 1);
            a11 += __shfl_xor_sync(0xffffffffu, a11, 2);
            if (q == 0) {
                sm[OFF_PT + r0] = a00 * sm[OFF_D0 + r0];
                sm[OFF_PT + r1] = a01 * sm[OFF_D0 + r1];
                sm[OFF_PT + kH + r0] = a10 * sm[OFF_D0 + r0];
                sm[OFF_PT + kH + r1] = a11 * sm[OFF_D0 + r1];
            }
        }
        __syncthreads();

        // --- F: ut_c = D1 .* (Wv1 pt_c), 2 channels
        {
            const float4* pt4 = (const float4*)&sm[OFF_PT];
            float a00 = 0.f, a01 = 0.f, a10 = 0.f, a11 = 0.f;
            #pragma unroll
            for (int j = 0; j < 8; j++) {
                float4 v0 = pt4[q * 8 + j];
                float4 v1 = pt4[32 + q * 8 + j];
                a00 = dot4(w1r[j], v0, a00);
                a01 = dot4(w1r[8 + j], v0, a01);
                a10 = dot4(w1r[j], v1, a10);
                a11 = dot4(w1r[8 + j], v1, a11);
            }
            a00 += __shfl_xor_sync(0xffffffffu, a00, 1);
            a00 += __shfl_xor_sync(0xffffffffu, a00, 2);
            a01 += __shfl_xor_sync(0xffffffffu, a01, 1);
            a01 += __shfl_xor_sync(0xffffffffu, a01, 2);
            a10 += __shfl_xor_sync(0xffffffffu, a10, 1);
            a10 += __shfl_xor_sync(0xffffffffu, a10, 2);
            a11 += __shfl_xor_sync(0xffffffffu, a11, 1);
            a11 += __shfl_xor_sync(0xffffffffu, a11, 2);
            if (q == 0) {
                sm[OFF_UT + r0] = a00 * sm[OFF_D1 + r0];
                sm[OFF_UT + r1] = a01 * sm[OFF_D1 + r1];
                sm[OFF_UT + kH + r0] = a10 * sm[OFF_D1 + r0];
                sm[OFF_UT + kH + r1] = a11 * sm[OFF_D1 + r1];
            }
        }
        __syncthreads();

        // --- G: rd = TD .* (Wv2s ut_{dl(row)})
        {
            int dl = w >> 2;   // rows 16w.. are in channel (r0>>6)
            const float4* u4 = (const float4*)&sm[OFF_UT + dl * kH];
            float acc0 = 0.f, acc1 = 0.f;
            #pragma unroll
            for (int j = 0; j < 8; j++) {
                float4 uv = u4[q * 8 + j];
                acc0 = dot4(w2r[j], uv, acc0);
                acc1 = dot4(w2r[8 + j], uv, acc1);
            }
            acc0 += __shfl_xor_sync(0xffffffffu, acc0, 1);
            acc0 += __shfl_xor_sync(0xffffffffu, acc0, 2);
            acc1 += __shfl_xor_sync(0xffffffffu, acc1, 1);
            acc1 += __shfl_xor_sync(0xffffffffu, acc1, 2);
            if (q == 0) {
                sm[OFF_RD + r0] = acc0 * sm[OFF_TDS + r0];
                sm[OFF_RD + r1] = acc1 * sm[OFF_TDS + r1];
            }
        }
        __syncthreads();
        // R exchange: fold 2 channels, push 64 floats, per-lane release arrives
        if (t < 16) {
            float4 x0 = rd4[t], x1 = rd4[16 + t];
            float4 rs = make_float4(x0.x + x1.x, x0.y + x1.y,
                                    x0.z + x1.z, x0.w + x1.w);
            int idx = 16 * rank + t;
            rslot4[idx] = rs;
            ((float4*)peer[0])[(OFF_RSLOT >> 2) + idx] = rs;
            ((float4*)peer[1])[(OFF_RSLOT >> 2) + idx] = rs;
            ((float4*)peer[2])[(OFF_RSLOT >> 2) + idx] = rs;
            #pragma unroll
            for (int p = 0; p < CL; p++) mbar_arrive_rel_cluster(rbar_r[p]);
        }
        mbar_wait_parity_cluster(rbar_l, par);

        // --- H: h += a.V + sum_r rslot
        if (t < kS) {
            float acc = sm[OFF_H + t];
            #pragma unroll
            for (int d = 0; d < kD; d++)
                acc = fmaf(sgn[d], sm[OFF_V + parV + d * kS + t], acc);
            #pragma unroll
            for (int p = 0; p < CL; p++)
                acc += sm[OFF_RSLOT + p * kS + t];
            sm[OFF_H + t] = acc;
        }
        __syncthreads();
    }

    // final readout (n = NWIN), rank 0 only
    if (rank == 0 && t < kOut) {
        float acc = sm[OFF_BR + t];
        #pragma unroll
        for (int a = 0; a < kS; a++)
            acc = fmaf(sm[OFF_WR + t * kS + a], sm[OFF_H + a], acc);
        out[((size_t)b * (kNW + 1) + kNW) * kOut + t] = acc;
    }
    cluster.sync();   // no CTA exits while peers may still write its smem
}

extern "C" void kernel_launch(void* const* d_in, const int* in_sizes, int n_in,
                              void* d_out, int out_size) {
    // metadata order: ts, x, Wi0,bi0, Wi1,bi1, Wi2,bi2, Wv0,bv0, Wv1,bv1, Wv2,bv2, Wr,br
    const float* x   = (const float*)d_in[1];
    const float* Wi0 = (const float*)d_in[2];
    const float* bi0 = (const float*)d_in[3];
    const float* Wi1 = (const float*)d_in[4];
    const float* bi1 = (const float*)d_in[5];
    const float* Wi2 = (const float*)d_in[6];
    const float* bi2 = (const float*)d_in[7];
    const float* Wv0 = (const float*)d_in[8];
    const float* bv0 = (const float*)d_in[9];
    const float* Wv1 = (const float*)d_in[10];
    const float* bv1 = (const float*)d_in[11];
    const float* Wv2 = (const float*)d_in[12];
    const float* bv2 = (const float*)d_in[13];
    const float* Wr  = (const float*)d_in[14];
    const float* br  = (const float*)d_in[15];
    float* out = (float*)d_out;

    cudaFuncSetAttribute(logncde_shfl_kernel,
                         cudaFuncAttributeMaxDynamicSharedMemorySize,
                         SMEMF * (int)sizeof(float));
    logncde_shfl_kernel<<<kB * CL, NT, SMEMF * sizeof(float)>>>(
        x, Wi0, bi0, Wi1, bi1, Wi2, bi2,
        Wv0, bv0, Wv1, bv1, Wv2, bv2, Wr, br, out);
}

// round 5
// speedup vs baseline: 1.9591x; 1.9591x over previous
#include <cuda_runtime.h>
#include <cooperative_groups.h>
#include <math.h>
#include <stdint.h>

namespace cg = cooperative_groups;

// ---------------------------------------------------------------------------
// LogNCDE depth-2 log-ODE scan, 4-CTA cluster per batch element.
// Rank r owns channels {2r,2r+1} and Wv2 rows [128r,128r+128).
// Weights in registers (row-pair x k-quarter tiles), partials reduced via smem
// (depth-4 trees). Cluster exchanges: DSMEM stores + single-arrive mbarriers.
// Readout + C coeffs hoisted out of the scan loop.
// ---------------------------------------------------------------------------

namespace {
constexpr int kB   = 32;
constexpr int kT   = 2049;
constexpr int kD   = 8;
constexpr int kS   = 64;
constexpr int kH   = 128;
constexpr int kP   = 28;
constexpr int kNW  = 128;
constexpr int kWin = 16;
constexpr int kOut = 8;
constexpr int CL   = 4;
constexpr int NT   = 256;

// shared-memory layout (float offsets; float4-aligned)
constexpr int OFF_SIGS  = 0;        // [n<128][36]
constexpr int OFF_CH    = 4608;     // [n<128][16] per-rank C coeffs
constexpr int OFF_BV0   = 6656;     // 128
constexpr int OFF_BV1   = 6784;     // 128
constexpr int OFF_BV2S  = 6912;     // 128
constexpr int OFF_WR    = 7040;     // [o<8][a<64]
constexpr int OFF_BR    = 7552;     // 8 (+pad)
constexpr int OFF_HH    = 7568;     // [n<129][64] h history
constexpr int OFF_Z0    = 15824;    // 128
constexpr int OFF_D0    = 15952;    // 128
constexpr int OFF_Z1    = 16080;    // 128
constexpr int OFF_D1    = 16208;    // 128
constexpr int OFF_V     = 16336;    // 2 x 512 double buffer
constexpr int OFF_TDS   = 17360;    // 128
constexpr int OFF_WT    = 17488;    // 2 x 64
constexpr int OFF_PT    = 17616;    // 2 x 128
constexpr int OFF_UT    = 17872;    // 2 x 128
constexpr int OFF_RSLOT = 18128;    // 4 x 64
constexpr int OFF_PART  = 18384;    // 2 x 4 x 128
constexpr int OFF_MBAR  = 19408;    // 16 B: VBAR @ +0, RBAR @ +8
constexpr int SMEMF     = 19412;    // ~76 KB
}  // namespace

static __device__ const int c_II[kP] =
    {0,0,0,0,0,0,0,1,1,1,1,1,1,2,2,2,2,2,3,3,3,3,4,4,4,5,5,6};
static __device__ const int c_JJ[kP] =
    {1,2,3,4,5,6,7,2,3,4,5,6,7,3,4,5,6,7,4,5,6,7,5,6,7,6,7,7};

__device__ __forceinline__ int pidx(int i, int j) {   // Lyndon pair index, i<j
    return 7 * i - (i * (i - 1)) / 2 + (j - i - 1);
}
__device__ __forceinline__ float dot4(float4 w, float4 v, float acc) {
    acc = fmaf(w.x, v.x, acc); acc = fmaf(w.y, v.y, acc);
    acc = fmaf(w.z, v.z, acc); acc = fmaf(w.w, v.w, acc);
    return acc;
}
__device__ __forceinline__ float tanh_ap(float x) {
    float r; asm("tanh.approx.f32 %0, %1;" : "=f"(r) : "f"(x)); return r;
}
// fast softplus value + sigmoid derivative from one exp
__device__ __forceinline__ void sp_sg(float s, float& z, float& d) {
    if (s > 20.f) { z = s; d = 1.f; }
    else {
        float e = __expf(s);
        float inv = __frcp_rn(1.f + e);
        z = __logf(1.f + e);
        d = e * inv;
    }
}
__device__ __forceinline__ float sp_f(float x) {   // accurate (one-time h0)
    return (x > 20.f) ? x : log1pf(expf(x));
}

__device__ __forceinline__ uint32_t cvta_smem(const void* p) {
    uint32_t a;
    asm("{ .reg .u64 t; cvta.to.shared.u64 t, %1; cvt.u32.u64 %0, t; }"
        : "=r"(a) : "l"(p));
    return a;
}
__device__ __forceinline__ uint32_t mapa_u32(uint32_t addr, int rank) {
    uint32_t r;
    asm("mapa.shared::cluster.u32 %0, %1, %2;" : "=r"(r) : "r"(addr), "r"(rank));
    return r;
}
__device__ __forceinline__ void mbar_init(uint32_t addr, uint32_t count) {
    asm volatile("mbarrier.init.shared.b64 [%0], %1;" :: "r"(addr), "r"(count) : "memory");
}
__device__ __forceinline__ void mbar_arrive_rel_cluster(uint32_t addr) {
    asm volatile("mbarrier.arrive.release.cluster.shared::cluster.b64 _, [%0];"
                 :: "r"(addr) : "memory");
}
__device__ __forceinline__ void mbar_wait_parity_cluster(uint32_t addr, uint32_t par) {
    uint32_t done;
    asm volatile(
        "{\n\t.reg .pred p;\n\t"
        "mbarrier.try_wait.parity.acquire.cluster.shared::cta.b64 p, [%1], %2;\n\t"
        "selp.b32 %0, 1, 0, p;\n\t}"
        : "=r"(done) : "r"(addr), "r"(par) : "memory");
    if (!done) {
        asm volatile(
            "{\n\t.reg .pred P1;\n\t"
            "WL_%=:\n\t"
            "mbarrier.try_wait.parity.acquire.cluster.shared::cta.b64 P1, [%0], %1, 0x989680;\n\t"
            "@P1 bra.uni WD_%=;\n\t"
            "bra.uni WL_%=;\n\t"
            "WD_%=:\n\t}"
            :: "r"(addr), "r"(par) : "memory");
    }
}

__global__ __launch_bounds__(NT, 1) __cluster_dims__(CL, 1, 1)
void logncde_v5_kernel(
    const float* __restrict__ x,
    const float* __restrict__ Wi0, const float* __restrict__ bi0,
    const float* __restrict__ Wi1, const float* __restrict__ bi1,
    const float* __restrict__ Wi2, const float* __restrict__ bi2,
    const float* __restrict__ Wv0, const float* __restrict__ bv0,
    const float* __restrict__ Wv1, const float* __restrict__ bv1,
    const float* __restrict__ Wv2, const float* __restrict__ bv2,
    const float* __restrict__ Wr,  const float* __restrict__ br,
    float* __restrict__ out)
{
    extern __shared__ float sm[];
    cg::cluster_group cluster = cg::this_cluster();
    const int t    = threadIdx.x;
    const int rank = (int)cluster.block_rank();
    const int b    = blockIdx.x >> 2;
    const int d0g  = 2 * rank;
    const int og2  = t & 63;          // row-pair id: rows 2*og2, 2*og2+1
    const int kg   = t >> 6;          // k-quarter (0..3)
    const int r0   = 2 * og2;
    const int r1   = r0 + 1;

    // peer data pointers
    float* peer[CL - 1];
    #pragma unroll
    for (int p = 1; p < CL; p++)
        peer[p - 1] = cluster.map_shared_rank(sm, (rank + p) & (CL - 1));

    // mbarriers: local + mapped to every rank
    const uint32_t smb    = cvta_smem(sm);
    const uint32_t vbar_l = smb + OFF_MBAR * 4;
    const uint32_t rbar_l = vbar_l + 8;
    uint32_t vbar_r[CL], rbar_r[CL];
    #pragma unroll
    for (int p = 0; p < CL; p++) {
        vbar_r[p] = mapa_u32(vbar_l, p);
        rbar_r[p] = mapa_u32(rbar_l, p);
    }
    if (t == 0) {
        mbar_init(vbar_l, CL);   // one arrive per rank
        mbar_init(rbar_l, CL);
        asm volatile("fence.mbarrier_init.release.cluster;" ::: "memory");
    }

    // ---- register weight tiles: rows (r0,r1) x k-quarter kg ----
    float4 w0r[8], w1r[16], w2r[16];
    {
        const float4* W0 = (const float4*)Wv0;   // [128][16] f4
        #pragma unroll
        for (int j = 0; j < 4; j++) {
            w0r[j]     = W0[r0 * 16 + kg * 4 + j];
            w0r[4 + j] = W0[r1 * 16 + kg * 4 + j];
        }
        const float4* W1 = (const float4*)Wv1;   // [128][32] f4
        #pragma unroll
        for (int j = 0; j < 8; j++) {
            w1r[j]     = W1[r0 * 32 + kg * 8 + j];
            w1r[8 + j] = W1[r1 * 32 + kg * 8 + j];
        }
        const float4* W2 = (const float4*)Wv2;   // [512][32] f4
        #pragma unroll
        for (int j = 0; j < 8; j++) {
            w2r[j]     = W2[(kH * rank + r0) * 32 + kg * 8 + j];
            w2r[8 + j] = W2[(kH * rank + r1) * 32 + kg * 8 + j];
        }
    }

    // ---- one-time smem staging ----
    for (int i = t; i < kH; i += NT) {
        sm[OFF_BV0 + i]  = bv0[i];
        sm[OFF_BV1 + i]  = bv1[i];
        sm[OFF_BV2S + i] = bv2[kH * rank + i];
    }
    for (int i = t; i < kOut * kS; i += NT) sm[OFF_WR + i] = Wr[i];
    if (t < kOut) sm[OFF_BR + t] = br[t];

    // ---- one-time: depth-2 log-signatures (one window per thread) ----
    if (t < kNW) {
        const float* xb = x + (size_t)b * kT * kD + (size_t)t * kWin * kD;
        float cum[kD], prev[kD], Mm[kD * kD];
        #pragma unroll
        for (int i = 0; i < kD; i++) { cum[i] = 0.f; prev[i] = xb[i]; }
        #pragma unroll
        for (int i = 0; i < kD * kD; i++) Mm[i] = 0.f;
        for (int ww = 0; ww < kWin; ww++) {
            float dl[kD];
            #pragma unroll
            for (int j = 0; j < kD; j++) {
                float c = xb[(ww + 1) * kD + j];
                dl[j] = c - prev[j];
                prev[j] = c;
            }
            #pragma unroll
            for (int i = 0; i < kD; i++)
                #pragma unroll
                for (int j = 0; j < kD; j++)
                    Mm[i * kD + j] = fmaf(cum[i], dl[j], Mm[i * kD + j]);
            #pragma unroll
            for (int i = 0; i < kD; i++) cum[i] += dl[i];
        }
        float* sgw = &sm[OFF_SIGS + t * 36];
        #pragma unroll
        for (int i = 0; i < kD; i++) sgw[i] = cum[i];
        #pragma unroll
        for (int p = 0; p < kP; p++) {
            int i = c_II[p], j = c_JJ[p];
            sgw[8 + p] = 0.5f * (Mm[i * kD + j] - Mm[j * kD + i]);
        }
    }
    __syncthreads();

    // ---- one-time: precompute C coefficients for all steps ----
    for (int i = t; i < kNW * 16; i += NT) {
        int n = i >> 4, j = i & 15;
        int dl = j >> 3, e = j & 7;
        int d = d0g + dl;
        const float* sgn = &sm[OFF_SIGS + n * 36];
        float v = 0.f;
        if (e < d)      v =  sgn[8 + pidx(e, d)];
        else if (e > d) v = -sgn[8 + pidx(d, e)];
        sm[OFF_CH + n * 16 + dl * 8 + e] = v;
    }

    // ---- one-time: initial MLP h0 (accurate path; replicated) ----
    {
        const float* x0 = x + (size_t)b * kT * kD;
        if (t < kH) {
            float acc = bi0[t];
            #pragma unroll
            for (int k = 0; k < kD; k++) acc = fmaf(Wi0[t * kD + k], x0[k], acc);
            sm[OFF_Z0 + t] = sp_f(acc);
        }
        __syncthreads();
        if (t < kH) {
            float acc = bi1[t];
            #pragma unroll 16
            for (int k = 0; k < kH; k++) acc = fmaf(Wi1[t * kH + k], sm[OFF_Z0 + k], acc);
            sm[OFF_Z1 + t] = sp_f(acc);
        }
        __syncthreads();
        if (t < kS) {
            float acc = bi2[t];
            #pragma unroll 16
            for (int k = 0; k < kH; k++) acc = fmaf(Wi2[t * kH + k], sm[OFF_Z1 + k], acc);
            sm[OFF_HH + t] = acc;
        }
        __syncthreads();
    }

    cluster.sync();   // staging + mbarrier init visible cluster-wide

    float2* part2 = (float2*)&sm[OFF_PART];

    // ============================ scan loop ============================
    for (int n = 0; n < kNW; n++) {
        const float* hcur = &sm[OFF_HH + n * kS];
        const int parV = (n & 1) * 512;
        const uint32_t par = (uint32_t)(n & 1);

        // --- A: partials of z0 = Wv0 h
        {
            const float4* h4 = (const float4*)hcur;
            float a0 = 0.f, a1 = 0.f;
            #pragma unroll
            for (int j = 0; j < 4; j++) {
                float4 hv = h4[kg * 4 + j];
                a0 = dot4(w0r[j], hv, a0);
                a1 = dot4(w0r[4 + j], hv, a1);
            }
            part2[kg * 64 + og2] = make_float2(a0, a1);
        }
        __syncthreads();
        if (t < kH) {
            float s = sm[OFF_BV0 + t] + sm[OFF_PART + t] + sm[OFF_PART + 128 + t]
                    + sm[OFF_PART + 256 + t] + sm[OFF_PART + 384 + t];
            float z, d;
            sp_sg(s, z, d);
            sm[OFF_Z0 + t] = z; sm[OFF_D0 + t] = d;
        }
        __syncthreads();

        // --- B: partials of z1 = Wv1 z0
        {
            const float4* z4 = (const float4*)&sm[OFF_Z0];
            float a0 = 0.f, a1 = 0.f;
            #pragma unroll
            for (int j = 0; j < 8; j++) {
                float4 zv = z4[kg * 8 + j];
                a0 = dot4(w1r[j], zv, a0);
                a1 = dot4(w1r[8 + j], zv, a1);
            }
            part2[kg * 64 + og2] = make_float2(a0, a1);
        }
        __syncthreads();
        if (t < kH) {
            float s = sm[OFF_BV1 + t] + sm[OFF_PART + t] + sm[OFF_PART + 128 + t]
                    + sm[OFF_PART + 256 + t] + sm[OFF_PART + 384 + t];
            float z, d;
            sp_sg(s, z, d);
            sm[OFF_Z1 + t] = z; sm[OFF_D1 + t] = d;
        }
        __syncthreads();

        // --- C: partials of V slice = Wv2s z1
        {
            const float4* z4 = (const float4*)&sm[OFF_Z1];
            float a0 = 0.f, a1 = 0.f;
            #pragma unroll
            for (int j = 0; j < 8; j++) {
                float4 zv = z4[kg * 8 + j];
                a0 = dot4(w2r[j], zv, a0);
                a1 = dot4(w2r[8 + j], zv, a1);
            }
            part2[kg * 64 + og2] = make_float2(a0, a1);
        }
        __syncthreads();
        if (t < kH) {
            float s = sm[OFF_BV2S + t] + sm[OFF_PART + t] + sm[OFF_PART + 128 + t]
                    + sm[OFF_PART + 256 + t] + sm[OFF_PART + 384 + t];
            float v = tanh_ap(s);
            int vi = OFF_V + parV + kH * rank + t;
            sm[vi] = v;
            sm[OFF_TDS + t] = 1.f - v * v;
            peer[0][vi] = v;
            peer[1][vi] = v;
            peer[2][vi] = v;
        }
        __syncthreads();
        if (t == 0) {
            #pragma unroll
            for (int p = 0; p < CL; p++) mbar_arrive_rel_cluster(vbar_r[p]);
        }
        mbar_wait_parity_cluster(vbar_l, par);

        // --- D: tangents w_dl = sum_e C[dl,e] V_e (own 2 channels)
        if (t < kH) {
            int dl = t >> 6, a_ = t & 63;
            const float* cj = &sm[OFF_CH + n * 16 + dl * 8];
            float acc = 0.f;
            #pragma unroll
            for (int e = 0; e < kD; e++)
                acc = fmaf(cj[e], sm[OFF_V + parV + e * kS + a_], acc);
            sm[OFF_WT + dl * kS + a_] = acc;
        }
        __syncthreads();

        // --- E: partials of q_c = Wv0 wt_c (2 channels)
        {
            const float4* wt4 = (const float4*)&sm[OFF_WT];
            float a00 = 0.f, a01 = 0.f, a10 = 0.f, a11 = 0.f;
            #pragma unroll
            for (int j = 0; j < 4; j++) {
                float4 v0 = wt4[kg * 4 + j];
                float4 v1 = wt4[16 + kg * 4 + j];
                a00 = dot4(w0r[j], v0, a00);
                a01 = dot4(w0r[4 + j], v0, a01);
                a10 = dot4(w0r[j], v1, a10);
                a11 = dot4(w0r[4 + j], v1, a11);
            }
            part2[kg * 64 + og2] = make_float2(a00, a01);
            part2[256 + kg * 64 + og2] = make_float2(a10, a11);
        }
        __syncthreads();
        {   // pt_c = D0 .* q_c  (all 256 threads)
            int dl = t >> 7, o = t & 127;
            float s = sm[OFF_PART + dl * 512 + o] + sm[OFF_PART + dl * 512 + 128 + o]
                    + sm[OFF_PART + dl * 512 + 256 + o] + sm[OFF_PART + dl * 512 + 384 + o];
            sm[OFF_PT + dl * kH + o] = s * sm[OFF_D0 + o];
        }
        __syncthreads();

        // --- F: partials of u'_c = Wv1 pt_c (2 channels)
        {
            const float4* pt4 = (const float4*)&sm[OFF_PT];
            float a00 = 0.f, a01 = 0.f, a10 = 0.f, a11 = 0.f;
            #pragma unroll
            for (int j = 0; j < 8; j++) {
                float4 v0 = pt4[kg * 8 + j];
                float4 v1 = pt4[32 + kg * 8 + j];
                a00 = dot4(w1r[j], v0, a00);
                a01 = dot4(w1r[8 + j], v0, a01);
                a10 = dot4(w1r[j], v1, a10);
                a11 = dot4(w1r[8 + j], v1, a11);
            }
            part2[kg * 64 + og2] = make_float2(a00, a01);
            part2[256 + kg * 64 + og2] = make_float2(a10, a11);
        }
        __syncthreads();
        {   // ut_c = D1 .* u'_c
            int dl = t >> 7, o = t & 127;
            float s = sm[OFF_PART + dl * 512 + o] + sm[OFF_PART + dl * 512 + 128 + o]
                    + sm[OFF_PART + dl * 512 + 256 + o] + sm[OFF_PART + dl * 512 + 384 + o];
            sm[OFF_UT + dl * kH + o] = s * sm[OFF_D1 + o];
        }
        __syncthreads();

        // --- G: partials of r = Wv2s ut_{channel(row)}
        {
            int dl = og2 >> 5;
            const float4* u4 = (const float4*)&sm[OFF_UT + dl * kH];
            float a0 = 0.f, a1 = 0.f;
            #pragma unroll
            for (int j = 0; j < 8; j++) {
                float4 uv = u4[kg * 8 + j];
                a0 = dot4(w2r[j], uv, a0);
                a1 = dot4(w2r[8 + j], uv, a1);
            }
            part2[kg * 64 + og2] = make_float2(a0, a1);
        }
        __syncthreads();
        // G-reduce: TD, fold 2 channels, push to peers
        if (t < kS) {
            float s0 = sm[OFF_PART + t] + sm[OFF_PART + 128 + t]
                     + sm[OFF_PART + 256 + t] + sm[OFF_PART + 384 + t];
            float s1 = sm[OFF_PART + 64 + t] + sm[OFF_PART + 192 + t]
                     + sm[OFF_PART + 320 + t] + sm[OFF_PART + 448 + t];
            float rs = s0 * sm[OFF_TDS + t] + s1 * sm[OFF_TDS + kS + t];
            int ri = OFF_RSLOT + kS * rank + t;
            sm[ri] = rs;
            peer[0][ri] = rs;
            peer[1][ri] = rs;
            peer[2][ri] = rs;
        }
        __syncthreads();
        if (t == 0) {
            #pragma unroll
            for (int p = 0; p < CL; p++) mbar_arrive_rel_cluster(rbar_r[p]);
        }
        mbar_wait_parity_cluster(rbar_l, par);

        // --- H: h_{n+1} = h_n + a.V + sum_r rslot
        if (t < kS) {
            const float* sgn = &sm[OFF_SIGS + n * 36];
            float acc = hcur[t];
            #pragma unroll
            for (int d = 0; d < kD; d++)
                acc = fmaf(sgn[d], sm[OFF_V + parV + d * kS + t], acc);
            #pragma unroll
            for (int p = 0; p < CL; p++)
                acc += sm[OFF_RSLOT + p * kS + t];
            sm[OFF_HH + (n + 1) * kS + t] = acc;
        }
        __syncthreads();
    }

    // ---- readout of the full h history (rank 0, parallel GEMM) ----
    if (rank == 0) {
        for (int idx = t; idx < (kNW + 1) * kOut; idx += NT) {
            int n = idx >> 3, o = idx & 7;
            float acc = sm[OFF_BR + o];
            const float* hh = &sm[OFF_HH + n * kS];
            #pragma unroll 16
            for (int a = 0; a < kS; a++)
                acc = fmaf(sm[OFF_WR + o * kS + a], hh[a], acc);
            out[((size_t)b * (kNW + 1) + n) * kOut + o] = acc;
        }
    }
    cluster.sync();   // no CTA exits while peers may still touch its smem
}

extern "C" void kernel_launch(void* const* d_in, const int* in_sizes, int n_in,
                              void* d_out, int out_size) {
    // metadata order: ts, x, Wi0,bi0, Wi1,bi1, Wi2,bi2, Wv0,bv0, Wv1,bv1, Wv2,bv2, Wr,br
    const float* x   = (const float*)d_in[1];
    const float* Wi0 = (const float*)d_in[2];
    const float* bi0 = (const float*)d_in[3];
    const float* Wi1 = (const float*)d_in[4];
    const float* bi1 = (const float*)d_in[5];
    const float* Wi2 = (const float*)d_in[6];
    const float* bi2 = (const float*)d_in[7];
    const float* Wv0 = (const float*)d_in[8];
    const float* bv0 = (const float*)d_in[9];
    const float* Wv1 = (const float*)d_in[10];
    const float* bv1 = (const float*)d_in[11];
    const float* Wv2 = (const float*)d_in[12];
    const float* bv2 = (const float*)d_in[13];
    const float* Wr  = (const float*)d_in[14];
    const float* br  = (const float*)d_in[15];
    float* out = (float*)d_out;

    cudaFuncSetAttribute(logncde_v5_kernel,
                         cudaFuncAttributeMaxDynamicSharedMemorySize,
                         SMEMF * (int)sizeof(float));
    logncde_v5_kernel<<<kB * CL, NT, SMEMF * sizeof(float)>>>(
        x, Wi0, bi0, Wi1, bi1, Wi2, bi2,
        Wv0, bv0, Wv1, bv1, Wv2, bv2, Wr, br, out);
}

// round 6
// speedup vs baseline: 2.6829x; 1.3695x over previous
#include <cuda_runtime.h>
#include <cooperative_groups.h>
#include <math.h>
#include <stdint.h>

namespace cg = cooperative_groups;

// ---------------------------------------------------------------------------
// LogNCDE depth-2 log-ODE scan, 4-CTA cluster per batch element.
// Rank r owns channels {2r,2r+1} and Wv2 rows [128r,128r+128).
// v3 engine: register weight tiles (4 rows x k-octant), smem float4 partials,
// cluster.sync exchanges. v6: readout hoisted (h history), C precomputed,
// fast activations.
// ---------------------------------------------------------------------------

namespace {
constexpr int kB   = 32;
constexpr int kT   = 2049;
constexpr int kD   = 8;
constexpr int kS   = 64;
constexpr int kH   = 128;
constexpr int kP   = 28;
constexpr int kNW  = 128;
constexpr int kWin = 16;
constexpr int kOut = 8;
constexpr int CL   = 4;
constexpr int NT   = 256;

// shared-memory layout (float offsets; float4-aligned)
constexpr int OFF_SIGS  = 0;        // [n<128][36]
constexpr int OFF_CH    = 4608;     // [n<128][16] per-rank C coeffs
constexpr int OFF_BV0   = 6656;     // 128
constexpr int OFF_BV1   = 6784;     // 128
constexpr int OFF_BV2S  = 6912;     // 128
constexpr int OFF_WR    = 7040;     // [o<8][a<64]
constexpr int OFF_BR    = 7552;     // 8 (+pad)
constexpr int OFF_HH    = 7568;     // [n<129][64] h history
constexpr int OFF_Z0    = 15824;    // 128
constexpr int OFF_D0    = 15952;    // 128
constexpr int OFF_Z1    = 16080;    // 128
constexpr int OFF_D1    = 16208;    // 128
constexpr int OFF_V     = 16336;    // 2 x 512 double buffer
constexpr int OFF_TDS   = 17360;    // 128
constexpr int OFF_WT    = 17488;    // 2 x 64
constexpr int OFF_PT    = 17616;    // 2 x 128
constexpr int OFF_UT    = 17872;    // 2 x 128
constexpr int OFF_RSLOT = 18128;    // 4 x 64
constexpr int OFF_PART  = 18384;    // 2 x 8 x 128 partials
constexpr int SMEMF     = 20432;    // ~82 KB
}  // namespace

static __device__ const int c_II[kP] =
    {0,0,0,0,0,0,0,1,1,1,1,1,1,2,2,2,2,2,3,3,3,3,4,4,4,5,5,6};
static __device__ const int c_JJ[kP] =
    {1,2,3,4,5,6,7,2,3,4,5,6,7,3,4,5,6,7,4,5,6,7,5,6,7,6,7,7};

__device__ __forceinline__ int pidx(int i, int j) {   // Lyndon pair index, i<j
    return 7 * i - (i * (i - 1)) / 2 + (j - i - 1);
}
__device__ __forceinline__ float dot4(float4 w, float4 v, float acc) {
    acc = fmaf(w.x, v.x, acc); acc = fmaf(w.y, v.y, acc);
    acc = fmaf(w.z, v.z, acc); acc = fmaf(w.w, v.w, acc);
    return acc;
}
__device__ __forceinline__ float tanh_ap(float x) {
    float r; asm("tanh.approx.f32 %0, %1;" : "=f"(r) : "f"(x)); return r;
}
// fast softplus value + sigmoid derivative from one exp
__device__ __forceinline__ void sp_sg(float s, float& z, float& d) {
    if (s > 20.f) { z = s; d = 1.f; }
    else {
        float e = __expf(s);
        float inv = __frcp_rn(1.f + e);
        z = __logf(1.f + e);
        d = e * inv;
    }
}
__device__ __forceinline__ float sp_f(float x) {   // accurate (one-time h0)
    return (x > 20.f) ? x : log1pf(expf(x));
}

__global__ __launch_bounds__(NT, 1) __cluster_dims__(CL, 1, 1)
void logncde_v6_kernel(
    const float* __restrict__ x,
    const float* __restrict__ Wi0, const float* __restrict__ bi0,
    const float* __restrict__ Wi1, const float* __restrict__ bi1,
    const float* __restrict__ Wi2, const float* __restrict__ bi2,
    const float* __restrict__ Wv0, const float* __restrict__ bv0,
    const float* __restrict__ Wv1, const float* __restrict__ bv1,
    const float* __restrict__ Wv2, const float* __restrict__ bv2,
    const float* __restrict__ Wr,  const float* __restrict__ br,
    float* __restrict__ out)
{
    extern __shared__ float sm[];
    cg::cluster_group cluster = cg::this_cluster();
    const int t    = threadIdx.x;
    const int rank = (int)cluster.block_rank();
    const int b    = blockIdx.x >> 2;
    const int d0g  = 2 * rank;
    const int og   = t & 31;     // output group: rows 4og..4og+3
    const int kg   = t >> 5;     // k-octant == warp id (broadcast-friendly)

    float* peer[CL - 1];
    #pragma unroll
    for (int p = 1; p < CL; p++)
        peer[p - 1] = cluster.map_shared_rank(sm, (rank + p) & (CL - 1));

    // ---- register weight tiles (loaded once from gmem) ----
    // Wv0 [o<128][k<64]  : 4 rows x 8k  -> 8  float4
    // Wv1 [o<128][k<128] : 4 rows x 16k -> 16 float4
    // Wv2 slice [og<128][k<128] (global rows 128*rank+og) -> 16 float4
    float4 w0r[8], w1r[16], w2r[16];
    {
        const float4* W0 = (const float4*)Wv0;
        #pragma unroll
        for (int r = 0; r < 4; r++)
            #pragma unroll
            for (int j = 0; j < 2; j++)
                w0r[r * 2 + j] = W0[(4 * og + r) * 16 + kg * 2 + j];
        const float4* W1 = (const float4*)Wv1;
        #pragma unroll
        for (int r = 0; r < 4; r++)
            #pragma unroll
            for (int j = 0; j < 4; j++)
                w1r[r * 4 + j] = W1[(4 * og + r) * 32 + kg * 4 + j];
        const float4* W2 = (const float4*)Wv2;
        #pragma unroll
        for (int r = 0; r < 4; r++)
            #pragma unroll
            for (int j = 0; j < 4; j++)
                w2r[r * 4 + j] = W2[(kH * rank + 4 * og + r) * 32 + kg * 4 + j];
    }

    // ---- one-time smem staging: biases, readout, signatures ----
    for (int i = t; i < kH; i += NT) {
        sm[OFF_BV0 + i]  = bv0[i];
        sm[OFF_BV1 + i]  = bv1[i];
        sm[OFF_BV2S + i] = bv2[kH * rank + i];
    }
    for (int i = t; i < kOut * kS; i += NT) sm[OFF_WR + i] = Wr[i];
    if (t < kOut) sm[OFF_BR + t] = br[t];

    if (t < kNW) {
        const float* xb = x + (size_t)b * kT * kD + (size_t)t * kWin * kD;
        float cum[kD], prev[kD], Mm[kD * kD];
        #pragma unroll
        for (int i = 0; i < kD; i++) { cum[i] = 0.f; prev[i] = xb[i]; }
        #pragma unroll
        for (int i = 0; i < kD * kD; i++) Mm[i] = 0.f;
        for (int w = 0; w < kWin; w++) {
            float dl[kD];
            #pragma unroll
            for (int j = 0; j < kD; j++) {
                float c = xb[(w + 1) * kD + j];
                dl[j] = c - prev[j];
                prev[j] = c;
            }
            #pragma unroll
            for (int i = 0; i < kD; i++)
                #pragma unroll
                for (int j = 0; j < kD; j++)
                    Mm[i * kD + j] = fmaf(cum[i], dl[j], Mm[i * kD + j]);
            #pragma unroll
            for (int i = 0; i < kD; i++) cum[i] += dl[i];
        }
        float* sgw = &sm[OFF_SIGS + t * 36];
        #pragma unroll
        for (int i = 0; i < kD; i++) sgw[i] = cum[i];
        #pragma unroll
        for (int p = 0; p < kP; p++) {
            int i = c_II[p], j = c_JJ[p];
            sgw[8 + p] = 0.5f * (Mm[i * kD + j] - Mm[j * kD + i]);
        }
    }
    __syncthreads();

    // ---- one-time: precompute C coefficients for all steps ----
    for (int i = t; i < kNW * 16; i += NT) {
        int n = i >> 4, j = i & 15;
        int dl = j >> 3, e = j & 7;
        int d = d0g + dl;
        const float* sgn = &sm[OFF_SIGS + n * 36];
        float v = 0.f;
        if (e < d)      v =  sgn[8 + pidx(e, d)];
        else if (e > d) v = -sgn[8 + pidx(d, e)];
        sm[OFF_CH + n * 16 + dl * 8 + e] = v;
    }

    // ---- one-time: initial MLP h0 (accurate path; replicated) ----
    {
        const float* x0 = x + (size_t)b * kT * kD;
        if (t < kH) {
            float acc = bi0[t];
            #pragma unroll
            for (int k = 0; k < kD; k++) acc = fmaf(Wi0[t * kD + k], x0[k], acc);
            sm[OFF_Z0 + t] = sp_f(acc);
        }
        __syncthreads();
        if (t < kH) {
            float acc = bi1[t];
            #pragma unroll 16
            for (int k = 0; k < kH; k++) acc = fmaf(Wi1[t * kH + k], sm[OFF_Z0 + k], acc);
            sm[OFF_Z1 + t] = sp_f(acc);
        }
        __syncthreads();
        if (t < kS) {
            float acc = bi2[t];
            #pragma unroll 16
            for (int k = 0; k < kH; k++) acc = fmaf(Wi2[t * kH + k], sm[OFF_Z1 + k], acc);
            sm[OFF_HH + t] = acc;
        }
        __syncthreads();
    }

    cluster.sync();

    float4* part4 = (float4*)&sm[OFF_PART];

    // ============================ scan loop ============================
    for (int n = 0; n < kNW; n++) {
        const float* hcur = &sm[OFF_HH + n * kS];
        const int parV = (n & 1) * 512;

        // --- A: partials of z0 = Wv0 h  (weights in regs, h broadcast)
        {
            const float4* h4 = (const float4*)hcur;
            float4 a = make_float4(0.f, 0.f, 0.f, 0.f);
            #pragma unroll
            for (int j = 0; j < 2; j++) {
                float4 hv = h4[kg * 2 + j];
                a.x = dot4(w0r[0 * 2 + j], hv, a.x);
                a.y = dot4(w0r[1 * 2 + j], hv, a.y);
                a.z = dot4(w0r[2 * 2 + j], hv, a.z);
                a.w = dot4(w0r[3 * 2 + j], hv, a.w);
            }
            part4[kg * 32 + og] = a;
        }
        __syncthreads();
        if (t < kH) {
            float s = sm[OFF_BV0 + t];
            #pragma unroll
            for (int q = 0; q < 8; q++) s += sm[OFF_PART + q * kH + t];
            float z, d;
            sp_sg(s, z, d);
            sm[OFF_Z0 + t] = z; sm[OFF_D0 + t] = d;
        }
        __syncthreads();

        // --- B: partials of z1 = Wv1 z0
        {
            const float4* z4 = (const float4*)&sm[OFF_Z0];
            float4 a = make_float4(0.f, 0.f, 0.f, 0.f);
            #pragma unroll
            for (int j = 0; j < 4; j++) {
                float4 zv = z4[kg * 4 + j];
                a.x = dot4(w1r[0 * 4 + j], zv, a.x);
                a.y = dot4(w1r[1 * 4 + j], zv, a.y);
                a.z = dot4(w1r[2 * 4 + j], zv, a.z);
                a.w = dot4(w1r[3 * 4 + j], zv, a.w);
            }
            part4[kg * 32 + og] = a;
        }
        __syncthreads();
        if (t < kH) {
            float s = sm[OFF_BV1 + t];
            #pragma unroll
            for (int q = 0; q < 8; q++) s += sm[OFF_PART + q * kH + t];
            float z, d;
            sp_sg(s, z, d);
            sm[OFF_Z1 + t] = z; sm[OFF_D1 + t] = d;
        }
        __syncthreads();

        // --- C: partials of V slice = Wv2_slice z1
        {
            const float4* z4 = (const float4*)&sm[OFF_Z1];
            float4 a = make_float4(0.f, 0.f, 0.f, 0.f);
            #pragma unroll
            for (int j = 0; j < 4; j++) {
                float4 zv = z4[kg * 4 + j];
                a.x = dot4(w2r[0 * 4 + j], zv, a.x);
                a.y = dot4(w2r[1 * 4 + j], zv, a.y);
                a.z = dot4(w2r[2 * 4 + j], zv, a.z);
                a.w = dot4(w2r[3 * 4 + j], zv, a.w);
            }
            part4[kg * 32 + og] = a;
        }
        __syncthreads();
        if (t < kH) {
            float s = sm[OFF_BV2S + t];
            #pragma unroll
            for (int q = 0; q < 8; q++) s += sm[OFF_PART + q * kH + t];
            float v = tanh_ap(s);
            int vi = OFF_V + parV + kH * rank + t;
            sm[vi] = v;
            sm[OFF_TDS + t] = 1.f - v * v;
            peer[0][vi] = v;
            peer[1][vi] = v;
            peer[2][vi] = v;
        }
        cluster.sync();   // V(n) gathered everywhere

        // --- D: tangents w_dl = sum_e C[dl,e] V_e (own 2 channels)
        if (t < kH) {
            int dl = t >> 6, a_ = t & 63;
            const float* cj = &sm[OFF_CH + n * 16 + dl * 8];
            float acc = 0.f;
            #pragma unroll
            for (int e = 0; e < kD; e++)
                acc = fmaf(cj[e], sm[OFF_V + parV + e * kS + a_], acc);
            sm[OFF_WT + dl * kS + a_] = acc;
        }
        __syncthreads();

        // --- E: partials of q_c = Wv0 wt_c (2 channels, shared weight regs)
        {
            const float4* wt4 = (const float4*)&sm[OFF_WT];
            float4 a0 = make_float4(0.f, 0.f, 0.f, 0.f);
            float4 a1 = make_float4(0.f, 0.f, 0.f, 0.f);
            #pragma unroll
            for (int j = 0; j < 2; j++) {
                float4 v0 = wt4[kg * 2 + j];
                float4 v1 = wt4[16 + kg * 2 + j];
                a0.x = dot4(w0r[0 * 2 + j], v0, a0.x);
                a0.y = dot4(w0r[1 * 2 + j], v0, a0.y);
                a0.z = dot4(w0r[2 * 2 + j], v0, a0.z);
                a0.w = dot4(w0r[3 * 2 + j], v0, a0.w);
                a1.x = dot4(w0r[0 * 2 + j], v1, a1.x);
                a1.y = dot4(w0r[1 * 2 + j], v1, a1.y);
                a1.z = dot4(w0r[2 * 2 + j], v1, a1.z);
                a1.w = dot4(w0r[3 * 2 + j], v1, a1.w);
            }
            part4[kg * 32 + og] = a0;
            part4[256 + kg * 32 + og] = a1;
        }
        __syncthreads();
        {   // pt_c = D0 .* q_c  (all 256 threads)
            int dl = t >> 7, o = t & 127;
            float s = 0.f;
            #pragma unroll
            for (int q = 0; q < 8; q++)
                s += sm[OFF_PART + dl * 1024 + q * kH + o];
            sm[OFF_PT + dl * kH + o] = s * sm[OFF_D0 + o];
        }
        __syncthreads();

        // --- F: partials of u'_c = Wv1 pt_c (2 channels)
        {
            const float4* pt4 = (const float4*)&sm[OFF_PT];
            float4 a0 = make_float4(0.f, 0.f, 0.f, 0.f);
            float4 a1 = make_float4(0.f, 0.f, 0.f, 0.f);
            #pragma unroll
            for (int j = 0; j < 4; j++) {
                float4 v0 = pt4[kg * 4 + j];
                float4 v1 = pt4[32 + kg * 4 + j];
                a0.x = dot4(w1r[0 * 4 + j], v0, a0.x);
                a0.y = dot4(w1r[1 * 4 + j], v0, a0.y);
                a0.z = dot4(w1r[2 * 4 + j], v0, a0.z);
                a0.w = dot4(w1r[3 * 4 + j], v0, a0.w);
                a1.x = dot4(w1r[0 * 4 + j], v1, a1.x);
                a1.y = dot4(w1r[1 * 4 + j], v1, a1.y);
                a1.z = dot4(w1r[2 * 4 + j], v1, a1.z);
                a1.w = dot4(w1r[3 * 4 + j], v1, a1.w);
            }
            part4[kg * 32 + og] = a0;
            part4[256 + kg * 32 + og] = a1;
        }
        __syncthreads();
        {   // ut_c = D1 .* u'_c
            int dl = t >> 7, o = t & 127;
            float s = 0.f;
            #pragma unroll
            for (int q = 0; q < 8; q++)
                s += sm[OFF_PART + dl * 1024 + q * kH + o];
            sm[OFF_UT + dl * kH + o] = s * sm[OFF_D1 + o];
        }
        __syncthreads();

        // --- G: partials of r = Wv2_slice u_{dl(row)}  (row-dependent RHS)
        {
            int dl = og >> 4;   // rows 4og..4og+3 all in channel dl
            const float4* u4 = (const float4*)&sm[OFF_UT + dl * kH];
            float4 a = make_float4(0.f, 0.f, 0.f, 0.f);
            #pragma unroll
            for (int j = 0; j < 4; j++) {
                float4 uv = u4[kg * 4 + j];
                a.x = dot4(w2r[0 * 4 + j], uv, a.x);
                a.y = dot4(w2r[1 * 4 + j], uv, a.y);
                a.z = dot4(w2r[2 * 4 + j], uv, a.z);
                a.w = dot4(w2r[3 * 4 + j], uv, a.w);
            }
            part4[kg * 32 + og] = a;
        }
        __syncthreads();
        // G-reduce: apply TD, fold the 2 channels, push to peers
        if (t < kS) {
            float s0 = 0.f, s1 = 0.f;
            #pragma unroll
            for (int q = 0; q < 8; q++) {
                s0 += sm[OFF_PART + q * kH + t];
                s1 += sm[OFF_PART + q * kH + kS + t];
            }
            float rs = s0 * sm[OFF_TDS + t] + s1 * sm[OFF_TDS + kS + t];
            int ri = OFF_RSLOT + kS * rank + t;
            sm[ri] = rs;
            peer[0][ri] = rs;
            peer[1][ri] = rs;
            peer[2][ri] = rs;
        }
        cluster.sync();   // bracket partials gathered everywhere

        // --- H: h_{n+1} = h_n + a.V + sum_r rslot (replicated)
        if (t < kS) {
            const float* sgn = &sm[OFF_SIGS + n * 36];
            float acc = hcur[t];
            #pragma unroll
            for (int d = 0; d < kD; d++)
                acc = fmaf(sgn[d], sm[OFF_V + parV + d * kS + t], acc);
            #pragma unroll
            for (int p = 0; p < CL; p++)
                acc += sm[OFF_RSLOT + p * kS + t];
            sm[OFF_HH + (n + 1) * kS + t] = acc;
        }
        __syncthreads();
    }

    // ---- readout of the full h history (rank 0, parallel GEMM) ----
    if (rank == 0) {
        for (int idx = t; idx < (kNW + 1) * kOut; idx += NT) {
            int n = idx >> 3, o = idx & 7;
            float acc = sm[OFF_BR + o];
            const float* hh = &sm[OFF_HH + n * kS];
            #pragma unroll 16
            for (int a = 0; a < kS; a++)
                acc = fmaf(sm[OFF_WR + o * kS + a], hh[a], acc);
            out[((size_t)b * (kNW + 1) + n) * kOut + o] = acc;
        }
    }
    cluster.sync();   // no CTA exits while peers may still touch its smem
}

extern "C" void kernel_launch(void* const* d_in, const int* in_sizes, int n_in,
                              void* d_out, int out_size) {
    // metadata order: ts, x, Wi0,bi0, Wi1,bi1, Wi2,bi2, Wv0,bv0, Wv1,bv1, Wv2,bv2, Wr,br
    const float* x   = (const float*)d_in[1];
    const float* Wi0 = (const float*)d_in[2];
    const float* bi0 = (const float*)d_in[3];
    const float* Wi1 = (const float*)d_in[4];
    const float* bi1 = (const float*)d_in[5];
    const float* Wi2 = (const float*)d_in[6];
    const float* bi2 = (const float*)d_in[7];
    const float* Wv0 = (const float*)d_in[8];
    const float* bv0 = (const float*)d_in[9];
    const float* Wv1 = (const float*)d_in[10];
    const float* bv1 = (const float*)d_in[11];
    const float* Wv2 = (const float*)d_in[12];
    const float* bv2 = (const float*)d_in[13];
    const float* Wr  = (const float*)d_in[14];
    const float* br  = (const float*)d_in[15];
    float* out = (float*)d_out;

    cudaFuncSetAttribute(logncde_v6_kernel,
                         cudaFuncAttributeMaxDynamicSharedMemorySize,
                         SMEMF * (int)sizeof(float));
    logncde_v6_kernel<<<kB * CL, NT, SMEMF * sizeof(float)>>>(
        x, Wi0, bi0, Wi1, bi1, Wi2, bi2,
        Wv0, bv0, Wv1, bv1, Wv2, bv2, Wr, br, out);
}